// round 2
// baseline (speedup 1.0000x reference)
#include <cuda_runtime.h>

// Fixed shapes: B=8,H=8,L=1024,DK=1024,DV=64; L==DK.
#define NROWS 65536          // B*H*L rows of Q/K, each 1024 floats = 256 float4

// Scratch (__device__ globals per allocation-free rule)
__device__ float g_qrs[NROWS];  // rowsum_k of elu(Q)+1
__device__ float g_krs[NROWS];  // rowsum_k of elu(K)+1
__device__ float g_kcs[NROWS];  // colsum_l of elu(K)+1, layout [bh][k]

__global__ void init_kcs_kernel() {
    g_kcs[blockIdx.x * 1024 + threadIdx.x] = 0.0f;
}

// elu(x)+1 without predicates: max(x,0) + exp(min(x,0))
__device__ __forceinline__ float elu1(float x) {
    return fmaxf(x, 0.0f) + exp2f(fminf(x, 0.0f) * 1.4426950408889634f);
}

// One tile = 32 consecutive rows. 256 threads; thread t owns float4 column
// chunk t for every row (perfectly coalesced; column partials live in regs).
// Rowsum path: per-thread 4-elem partial -> smem (STS.32, no shuffles in the
// hot loop), then one 5-shuffle reduce per row at the end.
template <bool DO_COL>
__device__ __forceinline__ void reduce_tile(const float4* __restrict__ X,
                                            int bt, float* __restrict__ rs_out,
                                            float* __restrict__ sm) {
    const int t  = threadIdx.x;
    const int w  = t >> 5;
    const int ln = t & 31;
    const float4* p = X + (size_t)bt * 8192 + t;   // 32 rows * 256 f4/row

    float c0 = 0.f, c1 = 0.f, c2 = 0.f, c3 = 0.f;

#pragma unroll 8
    for (int r = 0; r < 32; r++) {
        float4 v = p[r * 256];
        float e0 = elu1(v.x), e1 = elu1(v.y), e2 = elu1(v.z), e3 = elu1(v.w);
        if (DO_COL) { c0 += e0; c1 += e1; c2 += e2; c3 += e3; }
        sm[r * 256 + t] = (e0 + e1) + (e2 + e3);
    }
    __syncthreads();

    // Warp w reduces rows 4w..4w+3 (256 partials each: 8 LDS + 5 SHFL)
#pragma unroll
    for (int rr = 0; rr < 4; rr++) {
        const int row = w * 4 + rr;
        float s = 0.f;
#pragma unroll
        for (int i = 0; i < 8; i++) s += sm[row * 256 + 32 * i + ln];
        s += __shfl_xor_sync(0xffffffffu, s, 16);
        s += __shfl_xor_sync(0xffffffffu, s, 8);
        s += __shfl_xor_sync(0xffffffffu, s, 4);
        s += __shfl_xor_sync(0xffffffffu, s, 2);
        s += __shfl_xor_sync(0xffffffffu, s, 1);
        if (ln == 0) rs_out[bt * 32 + row] = s;
    }

    if (DO_COL) {
        // 32 tiles per (b,h) collide per address over the whole kernel: cheap.
        float* base = g_kcs + (bt >> 5) * 1024 + t * 4;
        atomicAdd(base + 0, c0);
        atomicAdd(base + 1, c1);
        atomicAdd(base + 2, c2);
        atomicAdd(base + 3, c3);
    }
}

__global__ __launch_bounds__(256) void reduce_both_kernel(const float4* __restrict__ K,
                                                          const float4* __restrict__ Q) {
    __shared__ float sm[32 * 256];   // 32 KB
    const int bt = blockIdx.x;
    if (bt < 2048) reduce_tile<true >(K, bt,        g_krs, sm);
    else           reduce_tile<false>(Q, bt - 2048, g_qrs, sm);
}

// out[row, :] = Qrs*Krs / (Qrs*Kcs + eps) * V[row, :]
// 4 consecutive float4 per thread: one scalar fetch per 16 elements, 4 LDG.128
// in flight for MLP.
__global__ __launch_bounds__(256) void finalize_kernel(const float4* __restrict__ V,
                                                       float4* __restrict__ O) {
    const int i   = (blockIdx.x * 256 + threadIdx.x) * 4;  // float4 index
    const int row = i >> 4;                                 // 16 f4 per row
    const float q = g_qrs[row];
    const float k = g_krs[row];
    const float c = g_kcs[row];
    const float scale = __fdividef(q * k, fmaf(q, c, 1e-6f));
    float4 v0 = V[i + 0], v1 = V[i + 1], v2 = V[i + 2], v3 = V[i + 3];
    v0.x *= scale; v0.y *= scale; v0.z *= scale; v0.w *= scale;
    v1.x *= scale; v1.y *= scale; v1.z *= scale; v1.w *= scale;
    v2.x *= scale; v2.y *= scale; v2.z *= scale; v2.w *= scale;
    v3.x *= scale; v3.y *= scale; v3.z *= scale; v3.w *= scale;
    O[i + 0] = v0; O[i + 1] = v1; O[i + 2] = v2; O[i + 3] = v3;
}

extern "C" void kernel_launch(void* const* d_in, const int* in_sizes, int n_in,
                              void* d_out, int out_size) {
    const float4* Q = (const float4*)d_in[0];
    const float4* K = (const float4*)d_in[1];
    const float4* V = (const float4*)d_in[2];
    float4* O = (float4*)d_out;

    init_kcs_kernel<<<64, 1024>>>();
    reduce_both_kernel<<<4096, 256>>>(K, Q);
    finalize_kernel<<<1024, 256>>>(V, O);
}

// round 3
// speedup vs baseline: 1.1010x; 1.1010x over previous
#include <cuda_runtime.h>

// Fixed shapes: B=8,H=8,L=1024,DK=1024,DV=64; L==DK.
#define NROWS 65536          // B*H*L rows of Q/K, each 1024 floats = 256 float4

// Scratch (__device__ globals: zero-initialized at module load; g_kcs is
// restored to zero by finalize_kernel after each consume, so every graph
// replay sees the same initial state without a dedicated init launch).
__device__ float g_qrs[NROWS];  // rowsum_k of elu(Q)+1
__device__ float g_krs[NROWS];  // rowsum_k of elu(K)+1
__device__ float g_kcs[NROWS];  // colsum_l of elu(K)+1, layout [bh][k]

// elu(x)+1 without predicates: max(x,0) + exp(min(x,0))
__device__ __forceinline__ float elu1(float x) {
    return fmaxf(x, 0.0f) + exp2f(fminf(x, 0.0f) * 1.4426950408889634f);
}

// One tile = 32 consecutive rows; 256 threads; thread t owns float4 column
// chunk t for every row (coalesced). Per row: warp shuffle-reduce -> 8
// partials in smem, combined at the end. Column partials stay in registers
// across all 32 rows, flushed with 4 spread-address atomicAdds per thread.
template <bool DO_COL>
__device__ __forceinline__ void reduce_tile(const float4* __restrict__ X,
                                            int bt, float* __restrict__ rs_out,
                                            float* __restrict__ sm) {
    const int t  = threadIdx.x;
    const int w  = t >> 5;
    const int ln = t & 31;
    const float4* p = X + (size_t)bt * 8192 + t;   // 32 rows * 256 f4/row

    float c0 = 0.f, c1 = 0.f, c2 = 0.f, c3 = 0.f;

#pragma unroll 8
    for (int r = 0; r < 32; r++) {
        float4 v = p[r * 256];
        float e0 = elu1(v.x), e1 = elu1(v.y), e2 = elu1(v.z), e3 = elu1(v.w);
        if (DO_COL) { c0 += e0; c1 += e1; c2 += e2; c3 += e3; }
        float s = (e0 + e1) + (e2 + e3);
        s += __shfl_xor_sync(0xffffffffu, s, 16);
        s += __shfl_xor_sync(0xffffffffu, s, 8);
        s += __shfl_xor_sync(0xffffffffu, s, 4);
        s += __shfl_xor_sync(0xffffffffu, s, 2);
        s += __shfl_xor_sync(0xffffffffu, s, 1);
        if (ln == 0) sm[r * 8 + w] = s;
    }
    __syncthreads();

    if (t < 32) {
        float s = 0.f;
#pragma unroll
        for (int i = 0; i < 8; i++) s += sm[t * 8 + i];
        rs_out[bt * 32 + t] = s;
    }

    if (DO_COL) {
        float* base = g_kcs + (bt >> 5) * 1024 + t * 4;
        atomicAdd(base + 0, c0);
        atomicAdd(base + 1, c1);
        atomicAdd(base + 2, c2);
        atomicAdd(base + 3, c3);
    }
}

__global__ __launch_bounds__(256) void reduce_both_kernel(const float4* __restrict__ K,
                                                          const float4* __restrict__ Q) {
    __shared__ float sm[32 * 8];
    const int bt = blockIdx.x;
    if (bt < 2048) reduce_tile<true >(K, bt,        g_krs, sm);
    else           reduce_tile<false>(Q, bt - 2048, g_qrs, sm);
}

// out[row, :] = Qrs*Krs / (Qrs*Kcs + eps) * V[row, :]
// 4 consecutive float4 per thread (one scalar-set fetch per row, 4 LDG.128 in
// flight). After consuming g_kcs[row], lane (t&3)==0 clears it for the next
// replay — the 4 readers are consecutive lanes of one warp, and the clearing
// STG is a later instruction than the shared LDG, so the read wins.
__global__ __launch_bounds__(256) void finalize_kernel(const float4* __restrict__ V,
                                                       float4* __restrict__ O) {
    const int gi  = blockIdx.x * 256 + threadIdx.x;
    const int i   = gi * 4;          // float4 index
    const int row = i >> 4;          // 16 f4 per row
    const float q = g_qrs[row];
    const float k = g_krs[row];
    const float c = g_kcs[row];
    if ((gi & 3) == 0) g_kcs[row] = 0.0f;   // restore invariant for next call
    const float scale = __fdividef(q * k, fmaf(q, c, 1e-6f));
    float4 v0 = V[i + 0], v1 = V[i + 1], v2 = V[i + 2], v3 = V[i + 3];
    v0.x *= scale; v0.y *= scale; v0.z *= scale; v0.w *= scale;
    v1.x *= scale; v1.y *= scale; v1.z *= scale; v1.w *= scale;
    v2.x *= scale; v2.y *= scale; v2.z *= scale; v2.w *= scale;
    v3.x *= scale; v3.y *= scale; v3.z *= scale; v3.w *= scale;
    O[i + 0] = v0; O[i + 1] = v1; O[i + 2] = v2; O[i + 3] = v3;
}

extern "C" void kernel_launch(void* const* d_in, const int* in_sizes, int n_in,
                              void* d_out, int out_size) {
    const float4* Q = (const float4*)d_in[0];
    const float4* K = (const float4*)d_in[1];
    const float4* V = (const float4*)d_in[2];
    float4* O = (float4*)d_out;

    reduce_both_kernel<<<4096, 256>>>(K, Q);
    finalize_kernel<<<1024, 256>>>(V, O);
}

// round 7
// speedup vs baseline: 1.1084x; 1.0068x over previous
#include <cuda_runtime.h>

// Fixed shapes: B=8,H=8,L=1024,DK=1024,DV=64; L==DK.
#define NROWS 65536          // B*H*L rows of Q/K, 1024 floats = 256 float4 each

// __device__ globals: zeroed at module load; g_kcs restored to zero by
// finalize_kernel after each consume -> deterministic across graph replays.
__device__ float g_qrs[NROWS];
__device__ float g_krs[NROWS];
__device__ float g_kcs[NROWS];  // colsum, layout [bh][k]

// elu(x)+1 without predicates: max(x,0) + exp(min(x,0))
__device__ __forceinline__ float elu1(float x) {
    return fmaxf(x, 0.0f) + exp2f(fminf(x, 0.0f) * 1.4426950408889634f);
}

// One tile = 32 rows. 8 warps; warp w owns rows 4w..4w+3. Lane ln reads f4
// positions {ln+32j : j<8} of each row: 8 independent LDG.128, coalesced.
// Rowsum: register sum + ONE 5-shuffle chain per row (4 per warp total).
// Colsum (K only): 32 register accumulators per lane (lane->column map is
// row-invariant), cross-warp combine through smem, then 4 atomicAdds/thread.
template <bool DO_COL>
__device__ __forceinline__ void reduce_tile(const float4* __restrict__ X,
                                            int bt, float* __restrict__ rs_out,
                                            float4* __restrict__ scol) {
    const int t  = threadIdx.x;
    const int w  = t >> 5;
    const int ln = t & 31;
    const float4* p = X + (size_t)bt * 8192;     // 32 rows * 256 f4

    float cacc[32];
    if (DO_COL) {
#pragma unroll
        for (int i = 0; i < 32; i++) cacc[i] = 0.0f;
    }

#pragma unroll
    for (int rr = 0; rr < 4; rr++) {
        const int row = w * 4 + rr;
        float4 v[8];
#pragma unroll
        for (int j = 0; j < 8; j++) v[j] = p[row * 256 + ln + 32 * j];

        float s = 0.0f;
#pragma unroll
        for (int j = 0; j < 8; j++) {
            float e0 = elu1(v[j].x), e1 = elu1(v[j].y);
            float e2 = elu1(v[j].z), e3 = elu1(v[j].w);
            if (DO_COL) {
                cacc[4 * j + 0] += e0; cacc[4 * j + 1] += e1;
                cacc[4 * j + 2] += e2; cacc[4 * j + 3] += e3;
            }
            s += (e0 + e1) + (e2 + e3);
        }
        s += __shfl_xor_sync(0xffffffffu, s, 16);
        s += __shfl_xor_sync(0xffffffffu, s, 8);
        s += __shfl_xor_sync(0xffffffffu, s, 4);
        s += __shfl_xor_sync(0xffffffffu, s, 2);
        s += __shfl_xor_sync(0xffffffffu, s, 1);
        if (ln == 0) rs_out[bt * 32 + row] = s;
    }

    if (DO_COL) {
        // Warp w dumps its 32 partials as 8 float4 (conflict-free STS.128).
#pragma unroll
        for (int j = 0; j < 8; j++)
            scol[w * 256 + ln + 32 * j] =
                make_float4(cacc[4 * j], cacc[4 * j + 1],
                            cacc[4 * j + 2], cacc[4 * j + 3]);
        __syncthreads();
        // Thread t combines the 8 warps' partials for f4-column t.
        float4 a = scol[t];
#pragma unroll
        for (int ww = 1; ww < 8; ww++) {
            float4 b = scol[ww * 256 + t];
            a.x += b.x; a.y += b.y; a.z += b.z; a.w += b.w;
        }
        float* base = g_kcs + (bt >> 5) * 1024 + t * 4;
        atomicAdd(base + 0, a.x);
        atomicAdd(base + 1, a.y);
        atomicAdd(base + 2, a.z);
        atomicAdd(base + 3, a.w);
    }
}

__global__ __launch_bounds__(256) void reduce_both_kernel(const float4* __restrict__ K,
                                                          const float4* __restrict__ Q) {
    __shared__ float4 scol[8 * 256];   // 32 KB, used only on the K branch
    const int bt = blockIdx.x;
    if (bt < 2048) reduce_tile<true >(K, bt,        g_krs, scol);
    else           reduce_tile<false>(Q, bt - 2048, g_qrs, scol);
}

// out[row,:] = Qrs*Krs / (Qrs*Kcs + eps) * V[row,:].  1 float4/thread,
// grid 4096 (this shape measured 8.16us / 2.15TB/s in R1).  The 16 readers
// of a row are one half-warp; the clearing STG follows the LDG in program
// order, so the read-then-clear is race-free.
__global__ __launch_bounds__(256) void finalize_kernel(const float4* __restrict__ V,
                                                       float4* __restrict__ O) {
    const int i   = blockIdx.x * 256 + threadIdx.x;  // float4 index
    const int row = i >> 4;
    const float q = g_qrs[row];
    const float k = g_krs[row];
    const float c = g_kcs[row];
    if ((i & 15) == 0) g_kcs[row] = 0.0f;            // restore for next replay
    const float scale = __fdividef(q * k, fmaf(q, c, 1e-6f));
    float4 v = V[i];
    v.x *= scale; v.y *= scale; v.z *= scale; v.w *= scale;
    O[i] = v;
}

extern "C" void kernel_launch(void* const* d_in, const int* in_sizes, int n_in,
                              void* d_out, int out_size) {
    const float4* Q = (const float4*)d_in[0];
    const float4* K = (const float4*)d_in[1];
    const float4* V = (const float4*)d_in[2];
    float4* O = (float4*)d_out;

    reduce_both_kernel<<<4096, 256>>>(K, Q);
    finalize_kernel<<<4096, 256>>>(V, O);
}